// round 3
// baseline (speedup 1.0000x reference)
#include <cuda_runtime.h>

// ---------------------------------------------------------------------------
// FitTorch: per-edge radial-Bessel -> MLP(3->64->64->1) -> structure energy,
// forces = -dE/dx. eij depends ONLY on scalar r => tabulate f(r), f'(r) once
// per launch, cubic-Hermite interpolate per edge.
// NOTE: neighlist/indices are int32 (JAX x64 disabled downcasts int64).
// ---------------------------------------------------------------------------

#define N_TAB   1024
#define R_MIN   0.40f
#define R_MAX   3.10f
#define DR      ((R_MAX - R_MIN) / (float)(N_TAB - 1))
#define INV_DR  ((float)(N_TAB - 1) / (R_MAX - R_MIN))

__device__ float2 g_table[N_TAB];   // (f, df/dr)

// ---------------------------------------------------------------------------
// Table build: one block (64 threads) per table entry.
// Forward + analytic backward of the MLP at r = R_MIN + k*DR.
// ---------------------------------------------------------------------------
__global__ void build_table_kernel(const float* __restrict__ W0, const float* __restrict__ b0,
                                   const float* __restrict__ W1, const float* __restrict__ b1,
                                   const float* __restrict__ W2, const float* __restrict__ b2)
{
    __shared__ float sW1[64 * 65];   // padded: row j at j*65, conflict-free both ways
    __shared__ float sh_h0[64];
    __shared__ float sh_v[64];
    __shared__ float red[8];

    const int k = threadIdx.x;       // 0..63 : hidden unit index

    // stage W1 [64x64, row-major in->out] into padded shared, coalesced
    for (int idx = k; idx < 64 * 64; idx += 64) {
        int j = idx >> 6, c = idx & 63;
        sW1[j * 65 + c] = W1[idx];
    }
    __syncthreads();

    const float r = R_MIN + (float)blockIdx.x * DR;
    const float A = 1.04719755119659774615f;  // pi/3
    const float C = 0.81649658092772603273f;  // sqrt(2/3)
    float s1, c1, s2, c2, s3, c3;
    sincosf(A * r,        &s1, &c1);
    sincosf(2.0f * A * r, &s2, &c2);
    sincosf(3.0f * A * r, &s3, &c3);
    const float inv_r = 1.0f / r;
    const float bas1 = C * s1 * inv_r;
    const float bas2 = C * s2 * inv_r;
    const float bas3 = C * s3 * inv_r;

    // layer 0
    float z0 = b0[k];
    z0 = fmaf(bas1, W0[k],       z0);
    z0 = fmaf(bas2, W0[64 + k],  z0);
    z0 = fmaf(bas3, W0[128 + k], z0);
    const float sg0 = 1.0f / (1.0f + expf(-z0));
    const float h0  = z0 * sg0;
    sh_h0[k] = h0;
    __syncthreads();

    // layer 1
    float z1 = b1[k];
    #pragma unroll
    for (int j = 0; j < 64; ++j)
        z1 = fmaf(sh_h0[j], sW1[j * 65 + k], z1);
    const float sg1 = 1.0f / (1.0f + expf(-z1));
    const float h1  = z1 * sg1;

    // output layer + backward seed
    const float w2k = W2[k];
    float ep = h1 * w2k;                                    // partial of eij
    const float dsilu1 = sg1 * (1.0f + z1 * (1.0f - sg1));
    sh_v[k] = w2k * dsilu1;                                 // v = dE/dz1
    __syncthreads();

    // u_j = (W1 v)_j * silu'(z0_j)   (thread index doubles as j here)
    float u = 0.0f;
    #pragma unroll
    for (int kk = 0; kk < 64; ++kk)
        u = fmaf(sh_v[kk], sW1[k * 65 + kk], u);
    u *= sg0 * (1.0f + z0 * (1.0f - sg0));

    // dE/dbasis_n partials
    float d1 = W0[k]       * u;
    float d2 = W0[64 + k]  * u;
    float d3 = W0[128 + k] * u;

    // block reduce (2 warps of 32)
    #pragma unroll
    for (int off = 16; off; off >>= 1) {
        ep += __shfl_down_sync(0xffffffffu, ep, off);
        d1 += __shfl_down_sync(0xffffffffu, d1, off);
        d2 += __shfl_down_sync(0xffffffffu, d2, off);
        d3 += __shfl_down_sync(0xffffffffu, d3, off);
    }
    const int warp = k >> 5, lane = k & 31;
    if (lane == 0) {
        red[warp * 4 + 0] = ep;
        red[warp * 4 + 1] = d1;
        red[warp * 4 + 2] = d2;
        red[warp * 4 + 3] = d3;
    }
    __syncthreads();
    if (k == 0) {
        const float e  = red[0] + red[4] + b2[0];
        const float D1 = red[1] + red[5];
        const float D2 = red[2] + red[6];
        const float D3 = red[3] + red[7];
        // dbasis_n/dr = C*(n*A*cos(nAr)/r - sin(nAr)/r^2)
        const float inv_r2 = inv_r * inv_r;
        const float db1 = C * fmaf(A,        c1 * inv_r, -s1 * inv_r2);
        const float db2 = C * fmaf(2.0f * A, c2 * inv_r, -s2 * inv_r2);
        const float db3 = C * fmaf(3.0f * A, c3 * inv_r, -s3 * inv_r2);
        const float g = D1 * db1 + D2 * db2 + D3 * db3;
        g_table[blockIdx.x] = make_float2(e, g);
    }
}

// ---------------------------------------------------------------------------
// Edge kernel: one thread per edge. Hermite lookup, warp-aggregated scatter.
// d_out layout: [0, n_struct) energies, then forces [n_atoms*3].
// ---------------------------------------------------------------------------
__global__ void edge_kernel(const float* __restrict__ x,
                            const int* __restrict__ nl,        // [E,2] int32
                            const float* __restrict__ xneigh,  // [E,3]
                            const int* __restrict__ sidx,      // [E] int32
                            float* __restrict__ energy,
                            float* __restrict__ forces,
                            int n_edges)
{
    const int e = blockIdx.x * blockDim.x + threadIdx.x;
    if (e >= n_edges) return;

    const int i = nl[2 * e];
    const float xi = x[3 * i], yi = x[3 * i + 1], zi = x[3 * i + 2];
    const int eb = 3 * e;
    const float dx = xi - xneigh[eb];
    const float dy = yi - xneigh[eb + 1];
    const float dz = zi - xneigh[eb + 2];
    const float r2 = fmaf(dx, dx, fmaf(dy, dy, dz * dz));
    const float r  = sqrtf(r2);

    // cubic Hermite table lookup (clamped)
    float t = (r - R_MIN) * INV_DR;
    t = fminf(fmaxf(t, 0.0f), (float)(N_TAB - 1));
    int k = (int)t;
    k = min(k, N_TAB - 2);
    const float uu = t - (float)k;
    const float2 p0 = g_table[k];
    const float2 p1 = g_table[k + 1];
    const float m0 = p0.y * DR, m1 = p1.y * DR;
    const float d  = p1.x - p0.x;
    const float a  = 3.0f * d - 2.0f * m0 - m1;
    const float b  = m0 + m1 - 2.0f * d;
    const float f  = p0.x + uu * (m0 + uu * fmaf(uu, b, a));             // eij
    const float g  = (m0 + uu * fmaf(3.0f * uu, b, 2.0f * a)) * INV_DR; // d eij/dr

    const float coef = -100.0f * g / r;
    const float fx = coef * dx, fy = coef * dy, fz = coef * dz;
    const int s = sidx[e];

    const unsigned FULL = 0xffffffffu;
    const unsigned act = __activemask();

    if (act == FULL) {
        const unsigned mi = __match_any_sync(FULL, i);
        const unsigned ms = __match_any_sync(FULL, s);
        float rfx = fx, rfy = fy, rfz = fz, re = f;
        #pragma unroll
        for (int off = 16; off; off >>= 1) {
            rfx += __shfl_xor_sync(FULL, rfx, off);
            rfy += __shfl_xor_sync(FULL, rfy, off);
            rfz += __shfl_xor_sync(FULL, rfz, off);
            re  += __shfl_xor_sync(FULL, re,  off);
        }
        const int lane = threadIdx.x & 31;
        if (mi == FULL) {
            if (lane == 0) {
                atomicAdd(&forces[3 * i],     rfx);
                atomicAdd(&forces[3 * i + 1], rfy);
                atomicAdd(&forces[3 * i + 2], rfz);
            }
        } else {
            atomicAdd(&forces[3 * i],     fx);
            atomicAdd(&forces[3 * i + 1], fy);
            atomicAdd(&forces[3 * i + 2], fz);
        }
        if (ms == FULL) {
            if (lane == 0) atomicAdd(&energy[s], 100.0f * re);
        } else {
            atomicAdd(&energy[s], 100.0f * f);
        }
    } else {
        atomicAdd(&forces[3 * i],     fx);
        atomicAdd(&forces[3 * i + 1], fy);
        atomicAdd(&forces[3 * i + 2], fz);
        atomicAdd(&energy[s], 100.0f * f);
    }
}

// ---------------------------------------------------------------------------
extern "C" void kernel_launch(void* const* d_in, const int* in_sizes, int n_in,
                              void* d_out, int out_size)
{
    const float* x      = (const float*)d_in[0];
    const int*   nl     = (const int*)d_in[1];
    const float* xneigh = (const float*)d_in[2];
    const int*   sidx   = (const int*)d_in[3];
    // d_in[4] atoms_per_structure, d_in[5] types: unused (counts from in_sizes)
    const float* W0 = (const float*)d_in[6];
    const float* b0 = (const float*)d_in[7];
    const float* W1 = (const float*)d_in[8];
    const float* b1 = (const float*)d_in[9];
    const float* W2 = (const float*)d_in[10];
    const float* b2 = (const float*)d_in[11];

    float* out = (float*)d_out;
    const int n_struct = in_sizes[4];
    const int n_edges  = in_sizes[3];

    // zero energies + forces (d_out is poisoned)
    cudaMemsetAsync(d_out, 0, (size_t)out_size * sizeof(float), 0);

    build_table_kernel<<<N_TAB, 64>>>(W0, b0, W1, b1, W2, b2);

    const int threads = 256;
    const int blocks  = (n_edges + threads - 1) / threads;
    edge_kernel<<<blocks, threads>>>(x, nl, xneigh, sidx,
                                     out, out + n_struct, n_edges);
}